// round 3
// baseline (speedup 1.0000x reference)
#include <cuda_runtime.h>
#include <cuda_bf16.h>
#include <cstdint>
#include <cstddef>

// Problem constants (fixed by setup_inputs)
#define BB 2
#define SS 2048
#define DD 3584
#define HH 28
#define KVH 4
#define HDIM 128
#define NREP 7
#define MROWS (BB*SS)          // 4096
#define QN (HH*HDIM)           // 3584
#define KN (KVH*HDIM)          // 512
#define ATT_SCALE 0.08838834764831845f

// ---------------------------------------------------------------------------
// Scratch (device globals; allocation inside kernel_launch is forbidden).
// Referenced DIRECTLY from device code — no cudaGetSymbolAddress on host.
// ---------------------------------------------------------------------------
__device__ float g_q[(size_t)MROWS * QN];   // 4096 x 3584
__device__ float g_k[(size_t)MROWS * KN];   // 4096 x 512
__device__ float g_v[(size_t)MROWS * KN];   // 4096 x 512
__device__ float g_o[(size_t)MROWS * QN];   // 4096 x 3584  (attention output)

// Which scratch buffer a GEMM reads/writes (compile-time dispatch so the
// kernels never need scratch pointers passed from the host).
#define BUF_EXT 0
#define BUF_Q   1
#define BUF_K   2
#define BUF_V   3
#define BUF_O   4

__device__ __forceinline__ const float* src_buf(int sel, const float* ext) {
    switch (sel) {
        case BUF_Q: return g_q;
        case BUF_O: return g_o;
        default:    return ext;
    }
}
__device__ __forceinline__ float* dst_buf(int sel, float* ext) {
    switch (sel) {
        case BUF_Q: return g_q;
        case BUF_K: return g_k;
        case BUF_V: return g_v;
        case BUF_O: return g_o;
        default:    return ext;
    }
}

// ---------------------------------------------------------------------------
// NT SGEMM: C[m,n] = sum_k A[m*K+k]*B[n*K+k] (+ bias[n])
// 128x128 block tile, BK=16, 256 threads, 8x8 per thread.
// M,N multiples of 128; K multiple of 16 (true for all 4 uses).
// ---------------------------------------------------------------------------
__global__ __launch_bounds__(256) void sgemm_nt(
    const float* __restrict__ Aext, int a_sel,
    const float* __restrict__ B,
    const float* __restrict__ bias,
    float* __restrict__ Cext, int c_sel,
    int M, int N, int K)
{
    const float* A = src_buf(a_sel, Aext);
    float* C = dst_buf(c_sel, Cext);

    __shared__ float As[16][132];
    __shared__ float Bs[16][132];

    const int bm = blockIdx.y * 128;
    const int bn = blockIdx.x * 128;
    const int tid = threadIdx.x;
    const int tx = tid & 15;
    const int ty = tid >> 4;
    const int lr = tid >> 2;         // 0..63
    const int lc = (tid & 3) << 2;   // 0,4,8,12

    const float* Aptr = A + (size_t)(bm + lr) * K + lc;
    const float* Bptr = B + (size_t)(bn + lr) * K + lc;
    const size_t strideA = (size_t)64 * K;

    float acc[8][8];
#pragma unroll
    for (int i = 0; i < 8; i++)
#pragma unroll
        for (int j = 0; j < 8; j++) acc[i][j] = 0.f;

#pragma unroll 1
    for (int k0 = 0; k0 < K; k0 += 16) {
        float4 a0 = *(const float4*)(Aptr + k0);
        float4 a1 = *(const float4*)(Aptr + k0 + strideA);
        float4 b0 = *(const float4*)(Bptr + k0);
        float4 b1 = *(const float4*)(Bptr + k0 + strideA);
        __syncthreads();
        As[lc + 0][lr] = a0.x; As[lc + 1][lr] = a0.y; As[lc + 2][lr] = a0.z; As[lc + 3][lr] = a0.w;
        As[lc + 0][lr + 64] = a1.x; As[lc + 1][lr + 64] = a1.y; As[lc + 2][lr + 64] = a1.z; As[lc + 3][lr + 64] = a1.w;
        Bs[lc + 0][lr] = b0.x; Bs[lc + 1][lr] = b0.y; Bs[lc + 2][lr] = b0.z; Bs[lc + 3][lr] = b0.w;
        Bs[lc + 0][lr + 64] = b1.x; Bs[lc + 1][lr + 64] = b1.y; Bs[lc + 2][lr + 64] = b1.z; Bs[lc + 3][lr + 64] = b1.w;
        __syncthreads();

#pragma unroll
        for (int kk = 0; kk < 16; kk++) {
            float4 af0 = *(const float4*)&As[kk][ty * 8];
            float4 af1 = *(const float4*)&As[kk][ty * 8 + 4];
            float4 bf0 = *(const float4*)&Bs[kk][tx * 8];
            float4 bf1 = *(const float4*)&Bs[kk][tx * 8 + 4];
            float a[8] = {af0.x, af0.y, af0.z, af0.w, af1.x, af1.y, af1.z, af1.w};
            float bv[8] = {bf0.x, bf0.y, bf0.z, bf0.w, bf1.x, bf1.y, bf1.z, bf1.w};
#pragma unroll
            for (int i = 0; i < 8; i++)
#pragma unroll
                for (int j = 0; j < 8; j++)
                    acc[i][j] = fmaf(a[i], bv[j], acc[i][j]);
        }
    }

    float bvv[8];
    if (bias) {
#pragma unroll
        for (int j = 0; j < 8; j++) bvv[j] = bias[bn + tx * 8 + j];
    } else {
#pragma unroll
        for (int j = 0; j < 8; j++) bvv[j] = 0.f;
    }

#pragma unroll
    for (int i = 0; i < 8; i++) {
        float* crow = C + (size_t)(bm + ty * 8 + i) * N + bn + tx * 8;
        float4 c0, c1;
        c0.x = acc[i][0] + bvv[0]; c0.y = acc[i][1] + bvv[1];
        c0.z = acc[i][2] + bvv[2]; c0.w = acc[i][3] + bvv[3];
        c1.x = acc[i][4] + bvv[4]; c1.y = acc[i][5] + bvv[5];
        c1.z = acc[i][6] + bvv[6]; c1.w = acc[i][7] + bvv[7];
        *(float4*)(crow) = c0;
        *(float4*)(crow + 4) = c1;
    }
}

// ---------------------------------------------------------------------------
// RoPE: interleaved pairs (2d, 2d+1) per head, position = row % S (start_pos=0)
// Operates directly on g_q / g_k.
// ---------------------------------------------------------------------------
__global__ void rope_kernel(const float* __restrict__ fc, const float* __restrict__ fs)
{
    const int NQ = MROWS * HH * 64;
    int idx = blockIdx.x * 256 + threadIdx.x;
    if (idx < NQ) {
        int d = idx & 63;
        int h = (idx >> 6) % HH;
        int row = idx / (64 * HH);
        int s = row & (SS - 1);
        float c = fc[s * 64 + d], sn = fs[s * 64 + d];
        float* p = g_q + (size_t)row * QN + h * HDIM + 2 * d;
        float xr = p[0], xi = p[1];
        p[0] = xr * c - xi * sn;
        p[1] = xr * sn + xi * c;
    } else {
        int j = idx - NQ;  // < MROWS*KVH*64 by grid sizing
        int d = j & 63;
        int h = (j >> 6) & 3;
        int row = j >> 8;
        int s = row & (SS - 1);
        float c = fc[s * 64 + d], sn = fs[s * 64 + d];
        float* p = g_k + (size_t)row * KN + h * HDIM + 2 * d;
        float xr = p[0], xi = p[1];
        p[0] = xr * c - xi * sn;
        p[1] = xr * sn + xi * c;
    }
}

// ---------------------------------------------------------------------------
// Flash attention (fp32 SIMT). Block = (64 q-rows, one head, one batch).
// BM=BN=64, HD=128. 256 threads = 16x16; score tile 4x4/thread, O tile 4x8/thread.
// Smem: Qt[128][68] (transposed, pre-scaled), Kt[128][68], Vs[64][132], Ps[64][68].
// Reads g_q/g_k/g_v, writes g_o.
// ---------------------------------------------------------------------------
__global__ __launch_bounds__(256) void flash_kernel()
{
    extern __shared__ float sm[];
    float* Qt = sm;                 // 128*68
    float* Kt = sm + 8704;          // 128*68
    float* Vs = sm + 17408;         // 64*132
    float* Ps = sm + 25856;         // 64*68

    const int m0 = (gridDim.x - 1 - blockIdx.x) * 64;   // heavy blocks first
    const int h = blockIdx.y;
    const int b = blockIdx.z;
    const int kvh = h / NREP;
    const int tid = threadIdx.x;
    const int tx = tid & 15;
    const int ty = tid >> 4;

    // Load Q tile transposed (and pre-scale by 1/sqrt(HD))
    const float* qb = g_q + (size_t)(b * SS + m0) * QN + h * HDIM;
#pragma unroll
    for (int it = 0; it < 8; it++) {
        int e = it * 256 + tid;        // 0..2047 float4s
        int r = e >> 5;                // row 0..63
        int d4 = (e & 31) << 2;        // d 0..124
        float4 val = *(const float4*)(qb + (size_t)r * QN + d4);
        Qt[(d4 + 0) * 68 + r] = val.x * ATT_SCALE;
        Qt[(d4 + 1) * 68 + r] = val.y * ATT_SCALE;
        Qt[(d4 + 2) * 68 + r] = val.z * ATT_SCALE;
        Qt[(d4 + 3) * 68 + r] = val.w * ATT_SCALE;
    }

    float mrow[4], lrow[4];
#pragma unroll
    for (int i = 0; i < 4; i++) { mrow[i] = -1e30f; lrow[i] = 0.f; }
    float accO[4][8];
#pragma unroll
    for (int i = 0; i < 4; i++)
#pragma unroll
        for (int j = 0; j < 8; j++) accO[i][j] = 0.f;

    const int jcount = m0 / 64 + 1;  // causal
    for (int jt = 0; jt < jcount; jt++) {
        const int t0 = jt * 64;
        __syncthreads();  // protect Kt/Vs/Ps reuse (and Qt on first iter)

        const float* kb = g_k + (size_t)(b * SS + t0) * KN + kvh * HDIM;
        const float* vb = g_v + (size_t)(b * SS + t0) * KN + kvh * HDIM;
#pragma unroll
        for (int it = 0; it < 8; it++) {
            int e = it * 256 + tid;
            int r = e >> 5;
            int d4 = (e & 31) << 2;
            float4 val = *(const float4*)(kb + (size_t)r * KN + d4);
            Kt[(d4 + 0) * 68 + r] = val.x;
            Kt[(d4 + 1) * 68 + r] = val.y;
            Kt[(d4 + 2) * 68 + r] = val.z;
            Kt[(d4 + 3) * 68 + r] = val.w;
            float4 vv = *(const float4*)(vb + (size_t)r * KN + d4);
            *(float4*)&Vs[r * 132 + d4] = vv;
        }
        __syncthreads();

        // Score GEMM: S = (Q*scale) K^T, 4x4 per thread
        float sc[4][4];
#pragma unroll
        for (int i = 0; i < 4; i++)
#pragma unroll
            for (int j = 0; j < 4; j++) sc[i][j] = 0.f;
#pragma unroll 8
        for (int kk = 0; kk < 128; kk++) {
            float4 a = *(const float4*)&Qt[kk * 68 + ty * 4];
            float4 bv = *(const float4*)&Kt[kk * 68 + tx * 4];
            float av[4] = {a.x, a.y, a.z, a.w};
            float bb2[4] = {bv.x, bv.y, bv.z, bv.w};
#pragma unroll
            for (int i = 0; i < 4; i++)
#pragma unroll
                for (int j = 0; j < 4; j++)
                    sc[i][j] = fmaf(av[i], bb2[j], sc[i][j]);
        }

        // Causal mask (only matters on the diagonal tile)
        if (t0 == m0) {
#pragma unroll
            for (int i = 0; i < 4; i++)
#pragma unroll
                for (int j = 0; j < 4; j++)
                    if (t0 + tx * 4 + j > m0 + ty * 4 + i) sc[i][j] = -1e30f;
        }

        // Online softmax (rows live in 16-lane shfl groups)
        float alpha[4];
#pragma unroll
        for (int i = 0; i < 4; i++) {
            float rm = fmaxf(fmaxf(sc[i][0], sc[i][1]), fmaxf(sc[i][2], sc[i][3]));
            rm = fmaxf(rm, __shfl_xor_sync(0xffffffffu, rm, 1));
            rm = fmaxf(rm, __shfl_xor_sync(0xffffffffu, rm, 2));
            rm = fmaxf(rm, __shfl_xor_sync(0xffffffffu, rm, 4));
            rm = fmaxf(rm, __shfl_xor_sync(0xffffffffu, rm, 8));
            float mn = fmaxf(mrow[i], rm);
            alpha[i] = __expf(mrow[i] - mn);
            float rs = 0.f;
#pragma unroll
            for (int j = 0; j < 4; j++) {
                sc[i][j] = __expf(sc[i][j] - mn);
                rs += sc[i][j];
            }
            rs += __shfl_xor_sync(0xffffffffu, rs, 1);
            rs += __shfl_xor_sync(0xffffffffu, rs, 2);
            rs += __shfl_xor_sync(0xffffffffu, rs, 4);
            rs += __shfl_xor_sync(0xffffffffu, rs, 8);
            lrow[i] = lrow[i] * alpha[i] + rs;
            mrow[i] = mn;
        }
#pragma unroll
        for (int i = 0; i < 4; i++)
#pragma unroll
            for (int j = 0; j < 8; j++) accO[i][j] *= alpha[i];

        // Stage P transposed: Ps[t][r]
#pragma unroll
        for (int i = 0; i < 4; i++)
#pragma unroll
            for (int j = 0; j < 4; j++)
                Ps[(tx * 4 + j) * 68 + ty * 4 + i] = sc[i][j];
        __syncthreads();

        // PV GEMM: O[4 rows][8 cols] += P V
#pragma unroll 4
        for (int t = 0; t < 64; t++) {
            float4 p = *(const float4*)&Ps[t * 68 + ty * 4];
            float4 v0 = *(const float4*)&Vs[t * 132 + tx * 8];
            float4 v1 = *(const float4*)&Vs[t * 132 + tx * 8 + 4];
            float pv[4] = {p.x, p.y, p.z, p.w};
            float vv[8] = {v0.x, v0.y, v0.z, v0.w, v1.x, v1.y, v1.z, v1.w};
#pragma unroll
            for (int i = 0; i < 4; i++)
#pragma unroll
                for (int j = 0; j < 8; j++)
                    accO[i][j] = fmaf(pv[i], vv[j], accO[i][j]);
        }
    }

    // Finalize and store
#pragma unroll
    for (int i = 0; i < 4; i++) {
        float inv = 1.f / lrow[i];
        float* ob = g_o + (size_t)(b * SS + m0 + ty * 4 + i) * QN + h * HDIM + tx * 8;
        float4 r0, r1;
        r0.x = accO[i][0] * inv; r0.y = accO[i][1] * inv;
        r0.z = accO[i][2] * inv; r0.w = accO[i][3] * inv;
        r1.x = accO[i][4] * inv; r1.y = accO[i][5] * inv;
        r1.z = accO[i][6] * inv; r1.w = accO[i][7] * inv;
        *(float4*)(ob) = r0;
        *(float4*)(ob + 4) = r1;
    }
}

// ---------------------------------------------------------------------------
// kernel_launch: kernel launches only (plus one cudaFuncSetAttribute, which
// is an immediate host-side call, not a stream op). No symbol queries, no
// allocation, no sync, no memcpy.
// ---------------------------------------------------------------------------
extern "C" void kernel_launch(void* const* d_in, const int* in_sizes, int n_in,
                              void* d_out, int out_size)
{
    const float* x    = (const float*)d_in[0];
    const float* wq_w = (const float*)d_in[1];
    const float* wq_b = (const float*)d_in[2];
    const float* wk_w = (const float*)d_in[3];
    const float* wk_b = (const float*)d_in[4];
    const float* wv_w = (const float*)d_in[5];
    const float* wv_b = (const float*)d_in[6];
    const float* wo_w = (const float*)d_in[7];
    const float* fc   = (const float*)d_in[10];
    const float* fs   = (const float*)d_in[11];
    float* out = (float*)d_out;

    const int flash_smem = 30208 * 4;  // 120,832 bytes
    cudaFuncSetAttribute(flash_kernel, cudaFuncAttributeMaxDynamicSharedMemorySize, flash_smem);

    // QKV projections (into device-global scratch, selected by enum)
    sgemm_nt<<<dim3(QN / 128, MROWS / 128), 256>>>(x, BUF_EXT, wq_w, wq_b, nullptr, BUF_Q, MROWS, QN, DD);
    sgemm_nt<<<dim3(KN / 128, MROWS / 128), 256>>>(x, BUF_EXT, wk_w, wk_b, nullptr, BUF_K, MROWS, KN, DD);
    sgemm_nt<<<dim3(KN / 128, MROWS / 128), 256>>>(x, BUF_EXT, wv_w, wv_b, nullptr, BUF_V, MROWS, KN, DD);

    // RoPE on g_q and g_k (8,388,608 pair-elements total, exactly 32768 blocks)
    rope_kernel<<<(MROWS * HH * 64 + MROWS * KVH * 64) / 256, 256>>>(fc, fs);

    // Causal GQA flash attention: g_q,g_k,g_v -> g_o
    flash_kernel<<<dim3(SS / 64, HH, BB), 256, flash_smem>>>();

    // Output projection: g_o @ wo_w^T -> out
    sgemm_nt<<<dim3(QN / 128, MROWS / 128), 256>>>(nullptr, BUF_O, wo_w, nullptr, out, BUF_EXT, MROWS, QN, DD);
}

// round 5
// speedup vs baseline: 1.5774x; 1.5774x over previous
#include <cuda_runtime.h>
#include <cuda_bf16.h>
#include <cstdint>
#include <cstddef>

// Problem constants (fixed by setup_inputs)
#define BB 2
#define SS 2048
#define DD 3584
#define HH 28
#define KVH 4
#define HDIM 128
#define NREP 7
#define MROWS (BB*SS)          // 4096
#define QN (HH*HDIM)           // 3584
#define KN (KVH*HDIM)          // 512
#define ATT_SCALE 0.08838834764831845f

// ---------------------------------------------------------------------------
// Scratch (device globals; allocation inside kernel_launch is forbidden).
// Referenced DIRECTLY from device code — no cudaGetSymbolAddress on host.
// ---------------------------------------------------------------------------
__device__ float g_q[(size_t)MROWS * QN];   // 4096 x 3584
__device__ float g_k[(size_t)MROWS * KN];   // 4096 x 512
__device__ float g_v[(size_t)MROWS * KN];   // 4096 x 512
__device__ float g_o[(size_t)MROWS * QN];   // 4096 x 3584  (attention output)

#define BUF_EXT 0
#define BUF_Q   1
#define BUF_K   2
#define BUF_V   3
#define BUF_O   4

__device__ __forceinline__ const float* src_buf(int sel, const float* ext) {
    switch (sel) {
        case BUF_Q: return g_q;
        case BUF_O: return g_o;
        default:    return ext;
    }
}
__device__ __forceinline__ float* dst_buf(int sel, float* ext) {
    switch (sel) {
        case BUF_Q: return g_q;
        case BUF_K: return g_k;
        case BUF_V: return g_v;
        case BUF_O: return g_o;
        default:    return ext;
    }
}

__device__ __forceinline__ uint32_t f2tf32(float x) {
    uint32_t r;
    asm("cvt.rna.tf32.f32 %0, %1;" : "=r"(r) : "f"(x));
    return r;
}

// ---------------------------------------------------------------------------
// NT GEMM on tf32 tensor cores: C[m,n] = sum_k A[m,k]*B[n,k] (+ bias[n]).
// 128x128 block tile, BK=16, double-buffered smem, 256 threads = 8 warps.
// Warp grid 2x4: each warp owns 64x32 = 4x4 fragments of m16n8k8.
// Smem rows padded to 20 words: fragment LDS addr = 20*r + c -> (4r+t) mod 32
// distinct across the 8x4 lane grid => conflict-free.
// Requires: M%128==0, N%128==0, K%16==0 (all uses: K=3584).
// ---------------------------------------------------------------------------
__global__ __launch_bounds__(256) void gemm_tf32(
    const float* __restrict__ Aext, int a_sel,
    const float* __restrict__ B,
    const float* __restrict__ bias,
    float* __restrict__ Cext, int c_sel,
    int M, int N, int K)
{
    const float* A = src_buf(a_sel, Aext);
    float* C = dst_buf(c_sel, Cext);

    __shared__ uint32_t As[2][128][20];
    __shared__ uint32_t Bs[2][128][20];

    const int bm = blockIdx.y * 128;
    const int bn = blockIdx.x * 128;
    const int tid = threadIdx.x;
    const int warp = tid >> 5;
    const int lane = tid & 31;
    const int g = lane >> 2;        // groupID (row within fragment)
    const int t = lane & 3;         // thread-in-group (col within fragment)
    const int wm = (warp >> 2) * 64;  // warp m offset in tile
    const int wn = (warp & 3) * 32;   // warp n offset in tile

    // Global-load assignment: each thread loads 2 float4 (8 floats) of A and B
    const int lrow = tid >> 1;            // 0..127
    const int lcol = (tid & 1) * 8;       // 0 or 8
    const float* aRow = A + (size_t)(bm + lrow) * K + lcol;
    const float* bRow = B + (size_t)(bn + lrow) * K + lcol;

    float acc[4][4][4];
#pragma unroll
    for (int mi = 0; mi < 4; mi++)
#pragma unroll
        for (int ni = 0; ni < 4; ni++)
#pragma unroll
            for (int e = 0; e < 4; e++) acc[mi][ni][e] = 0.f;

    const int kIters = K >> 4;

    // Prologue: load tile 0
    {
        float4 a0 = *(const float4*)(aRow);
        float4 a1 = *(const float4*)(aRow + 4);
        float4 b0 = *(const float4*)(bRow);
        float4 b1 = *(const float4*)(bRow + 4);
        As[0][lrow][lcol + 0] = f2tf32(a0.x); As[0][lrow][lcol + 1] = f2tf32(a0.y);
        As[0][lrow][lcol + 2] = f2tf32(a0.z); As[0][lrow][lcol + 3] = f2tf32(a0.w);
        As[0][lrow][lcol + 4] = f2tf32(a1.x); As[0][lrow][lcol + 5] = f2tf32(a1.y);
        As[0][lrow][lcol + 6] = f2tf32(a1.z); As[0][lrow][lcol + 7] = f2tf32(a1.w);
        Bs[0][lrow][lcol + 0] = f2tf32(b0.x); Bs[0][lrow][lcol + 1] = f2tf32(b0.y);
        Bs[0][lrow][lcol + 2] = f2tf32(b0.z); Bs[0][lrow][lcol + 3] = f2tf32(b0.w);
        Bs[0][lrow][lcol + 4] = f2tf32(b1.x); Bs[0][lrow][lcol + 5] = f2tf32(b1.y);
        Bs[0][lrow][lcol + 6] = f2tf32(b1.z); Bs[0][lrow][lcol + 7] = f2tf32(b1.w);
    }
    __syncthreads();

    int buf = 0;
#pragma unroll 1
    for (int it = 0; it < kIters; it++) {
        const bool hasNext = (it + 1) < kIters;
        float4 a0, a1, b0, b1;
        if (hasNext) {
            const int k0 = (it + 1) << 4;
            a0 = *(const float4*)(aRow + k0);
            a1 = *(const float4*)(aRow + k0 + 4);
            b0 = *(const float4*)(bRow + k0);
            b1 = *(const float4*)(bRow + k0 + 4);
        }

        // Compute on current buffer: 2 k-steps of 8
#pragma unroll
        for (int ks = 0; ks < 16; ks += 8) {
            uint32_t af[4][4];
#pragma unroll
            for (int mi = 0; mi < 4; mi++) {
                const int r = wm + mi * 16;
                af[mi][0] = As[buf][r + g][ks + t];
                af[mi][1] = As[buf][r + g + 8][ks + t];
                af[mi][2] = As[buf][r + g][ks + t + 4];
                af[mi][3] = As[buf][r + g + 8][ks + t + 4];
            }
            uint32_t bfr[4][2];
#pragma unroll
            for (int ni = 0; ni < 4; ni++) {
                const int c = wn + ni * 8;
                bfr[ni][0] = Bs[buf][c + g][ks + t];
                bfr[ni][1] = Bs[buf][c + g][ks + t + 4];
            }
#pragma unroll
            for (int mi = 0; mi < 4; mi++)
#pragma unroll
                for (int ni = 0; ni < 4; ni++) {
                    asm volatile(
                        "mma.sync.aligned.m16n8k8.row.col.f32.tf32.tf32.f32 "
                        "{%0,%1,%2,%3}, {%4,%5,%6,%7}, {%8,%9}, {%0,%1,%2,%3};\n"
                        : "+f"(acc[mi][ni][0]), "+f"(acc[mi][ni][1]),
                          "+f"(acc[mi][ni][2]), "+f"(acc[mi][ni][3])
                        : "r"(af[mi][0]), "r"(af[mi][1]), "r"(af[mi][2]), "r"(af[mi][3]),
                          "r"(bfr[ni][0]), "r"(bfr[ni][1]));
                }
        }

        if (hasNext) {
            const int nb = buf ^ 1;
            As[nb][lrow][lcol + 0] = f2tf32(a0.x); As[nb][lrow][lcol + 1] = f2tf32(a0.y);
            As[nb][lrow][lcol + 2] = f2tf32(a0.z); As[nb][lrow][lcol + 3] = f2tf32(a0.w);
            As[nb][lrow][lcol + 4] = f2tf32(a1.x); As[nb][lrow][lcol + 5] = f2tf32(a1.y);
            As[nb][lrow][lcol + 6] = f2tf32(a1.z); As[nb][lrow][lcol + 7] = f2tf32(a1.w);
            Bs[nb][lrow][lcol + 0] = f2tf32(b0.x); Bs[nb][lrow][lcol + 1] = f2tf32(b0.y);
            Bs[nb][lrow][lcol + 2] = f2tf32(b0.z); Bs[nb][lrow][lcol + 3] = f2tf32(b0.w);
            Bs[nb][lrow][lcol + 4] = f2tf32(b1.x); Bs[nb][lrow][lcol + 5] = f2tf32(b1.y);
            Bs[nb][lrow][lcol + 6] = f2tf32(b1.z); Bs[nb][lrow][lcol + 7] = f2tf32(b1.w);
            __syncthreads();
            buf = nb;
        }
    }

    // Epilogue: acc[mi][ni] -> C rows (g, g+8), cols (2t, 2t+1), plus bias
#pragma unroll
    for (int ni = 0; ni < 4; ni++) {
        const int cc = bn + wn + ni * 8 + 2 * t;
        float2 bv = make_float2(0.f, 0.f);
        if (bias) bv = *(const float2*)(bias + cc);
#pragma unroll
        for (int mi = 0; mi < 4; mi++) {
            const int rr = bm + wm + mi * 16 + g;
            float2 c0, c1;
            c0.x = acc[mi][ni][0] + bv.x; c0.y = acc[mi][ni][1] + bv.y;
            c1.x = acc[mi][ni][2] + bv.x; c1.y = acc[mi][ni][3] + bv.y;
            *(float2*)(C + (size_t)rr * N + cc) = c0;
            *(float2*)(C + (size_t)(rr + 8) * N + cc) = c1;
        }
    }
}

// ---------------------------------------------------------------------------
// RoPE: interleaved pairs (2d, 2d+1) per head, position = row % S (start_pos=0)
// ---------------------------------------------------------------------------
__global__ void rope_kernel(const float* __restrict__ fc, const float* __restrict__ fs)
{
    const int NQ = MROWS * HH * 64;
    int idx = blockIdx.x * 256 + threadIdx.x;
    if (idx < NQ) {
        int d = idx & 63;
        int h = (idx >> 6) % HH;
        int row = idx / (64 * HH);
        int s = row & (SS - 1);
        float c = fc[s * 64 + d], sn = fs[s * 64 + d];
        float* p = g_q + (size_t)row * QN + h * HDIM + 2 * d;
        float xr = p[0], xi = p[1];
        p[0] = xr * c - xi * sn;
        p[1] = xr * sn + xi * c;
    } else {
        int j = idx - NQ;
        int d = j & 63;
        int h = (j >> 6) & 3;
        int row = j >> 8;
        int s = row & (SS - 1);
        float c = fc[s * 64 + d], sn = fs[s * 64 + d];
        float* p = g_k + (size_t)row * KN + h * HDIM + 2 * d;
        float xr = p[0], xi = p[1];
        p[0] = xr * c - xi * sn;
        p[1] = xr * sn + xi * c;
    }
}

// ---------------------------------------------------------------------------
// Flash attention (fp32 SIMT), unchanged from the passing R3 kernel.
// ---------------------------------------------------------------------------
__global__ __launch_bounds__(256) void flash_kernel()
{
    extern __shared__ float sm[];
    float* Qt = sm;                 // 128*68
    float* Kt = sm + 8704;          // 128*68
    float* Vs = sm + 17408;         // 64*132
    float* Ps = sm + 25856;         // 64*68

    const int m0 = (gridDim.x - 1 - blockIdx.x) * 64;   // heavy blocks first
    const int h = blockIdx.y;
    const int b = blockIdx.z;
    const int kvh = h / NREP;
    const int tid = threadIdx.x;
    const int tx = tid & 15;
    const int ty = tid >> 4;

    const float* qb = g_q + (size_t)(b * SS + m0) * QN + h * HDIM;
#pragma unroll
    for (int it = 0; it < 8; it++) {
        int e = it * 256 + tid;
        int r = e >> 5;
        int d4 = (e & 31) << 2;
        float4 val = *(const float4*)(qb + (size_t)r * QN + d4);
        Qt[(d4 + 0) * 68 + r] = val.x * ATT_SCALE;
        Qt[(d4 + 1) * 68 + r] = val.y * ATT_SCALE;
        Qt[(d4 + 2) * 68 + r] = val.z * ATT_SCALE;
        Qt[(d4 + 3) * 68 + r] = val.w * ATT_SCALE;
    }

    float mrow[4], lrow[4];
#pragma unroll
    for (int i = 0; i < 4; i++) { mrow[i] = -1e30f; lrow[i] = 0.f; }
    float accO[4][8];
#pragma unroll
    for (int i = 0; i < 4; i++)
#pragma unroll
        for (int j = 0; j < 8; j++) accO[i][j] = 0.f;

    const int jcount = m0 / 64 + 1;  // causal
    for (int jt = 0; jt < jcount; jt++) {
        const int t0 = jt * 64;
        __syncthreads();

        const float* kb = g_k + (size_t)(b * SS + t0) * KN + kvh * HDIM;
        const float* vb = g_v + (size_t)(b * SS + t0) * KN + kvh * HDIM;
#pragma unroll
        for (int it = 0; it < 8; it++) {
            int e = it * 256 + tid;
            int r = e >> 5;
            int d4 = (e & 31) << 2;
            float4 val = *(const float4*)(kb + (size_t)r * KN + d4);
            Kt[(d4 + 0) * 68 + r] = val.x;
            Kt[(d4 + 1) * 68 + r] = val.y;
            Kt[(d4 + 2) * 68 + r] = val.z;
            Kt[(d4 + 3) * 68 + r] = val.w;
            float4 vv = *(const float4*)(vb + (size_t)r * KN + d4);
            *(float4*)&Vs[r * 132 + d4] = vv;
        }
        __syncthreads();

        float sc[4][4];
#pragma unroll
        for (int i = 0; i < 4; i++)
#pragma unroll
            for (int j = 0; j < 4; j++) sc[i][j] = 0.f;
#pragma unroll 8
        for (int kk = 0; kk < 128; kk++) {
            float4 a = *(const float4*)&Qt[kk * 68 + ty * 4];
            float4 bv = *(const float4*)&Kt[kk * 68 + tx * 4];
            float av[4] = {a.x, a.y, a.z, a.w};
            float bb2[4] = {bv.x, bv.y, bv.z, bv.w};
#pragma unroll
            for (int i = 0; i < 4; i++)
#pragma unroll
                for (int j = 0; j < 4; j++)
                    sc[i][j] = fmaf(av[i], bb2[j], sc[i][j]);
        }

        if (t0 == m0) {
#pragma unroll
            for (int i = 0; i < 4; i++)
#pragma unroll
                for (int j = 0; j < 4; j++)
                    if (t0 + tx * 4 + j > m0 + ty * 4 + i) sc[i][j] = -1e30f;
        }

        float alpha[4];
#pragma unroll
        for (int i = 0; i < 4; i++) {
            float rm = fmaxf(fmaxf(sc[i][0], sc[i][1]), fmaxf(sc[i][2], sc[i][3]));
            rm = fmaxf(rm, __shfl_xor_sync(0xffffffffu, rm, 1));
            rm = fmaxf(rm, __shfl_xor_sync(0xffffffffu, rm, 2));
            rm = fmaxf(rm, __shfl_xor_sync(0xffffffffu, rm, 4));
            rm = fmaxf(rm, __shfl_xor_sync(0xffffffffu, rm, 8));
            float mn = fmaxf(mrow[i], rm);
            alpha[i] = __expf(mrow[i] - mn);
            float rs = 0.f;
#pragma unroll
            for (int j = 0; j < 4; j++) {
                sc[i][j] = __expf(sc[i][j] - mn);
                rs += sc[i][j];
            }
            rs += __shfl_xor_sync(0xffffffffu, rs, 1);
            rs += __shfl_xor_sync(0xffffffffu, rs, 2);
            rs += __shfl_xor_sync(0xffffffffu, rs, 4);
            rs += __shfl_xor_sync(0xffffffffu, rs, 8);
            lrow[i] = lrow[i] * alpha[i] + rs;
            mrow[i] = mn;
        }
#pragma unroll
        for (int i = 0; i < 4; i++)
#pragma unroll
            for (int j = 0; j < 8; j++) accO[i][j] *= alpha[i];

#pragma unroll
        for (int i = 0; i < 4; i++)
#pragma unroll
            for (int j = 0; j < 4; j++)
                Ps[(tx * 4 + j) * 68 + ty * 4 + i] = sc[i][j];
        __syncthreads();

#pragma unroll 4
        for (int t = 0; t < 64; t++) {
            float4 p = *(const float4*)&Ps[t * 68 + ty * 4];
            float4 v0 = *(const float4*)&Vs[t * 132 + tx * 8];
            float4 v1 = *(const float4*)&Vs[t * 132 + tx * 8 + 4];
            float pv[4] = {p.x, p.y, p.z, p.w};
            float vv[8] = {v0.x, v0.y, v0.z, v0.w, v1.x, v1.y, v1.z, v1.w};
#pragma unroll
            for (int i = 0; i < 4; i++)
#pragma unroll
                for (int j = 0; j < 8; j++)
                    accO[i][j] = fmaf(pv[i], vv[j], accO[i][j]);
        }
    }

#pragma unroll
    for (int i = 0; i < 4; i++) {
        float inv = 1.f / lrow[i];
        float* ob = g_o + (size_t)(b * SS + m0 + ty * 4 + i) * QN + h * HDIM + tx * 8;
        float4 r0, r1;
        r0.x = accO[i][0] * inv; r0.y = accO[i][1] * inv;
        r0.z = accO[i][2] * inv; r0.w = accO[i][3] * inv;
        r1.x = accO[i][4] * inv; r1.y = accO[i][5] * inv;
        r1.z = accO[i][6] * inv; r1.w = accO[i][7] * inv;
        *(float4*)(ob) = r0;
        *(float4*)(ob + 4) = r1;
    }
}

// ---------------------------------------------------------------------------
// kernel_launch
// ---------------------------------------------------------------------------
extern "C" void kernel_launch(void* const* d_in, const int* in_sizes, int n_in,
                              void* d_out, int out_size)
{
    const float* x    = (const float*)d_in[0];
    const float* wq_w = (const float*)d_in[1];
    const float* wq_b = (const float*)d_in[2];
    const float* wk_w = (const float*)d_in[3];
    const float* wk_b = (const float*)d_in[4];
    const float* wv_w = (const float*)d_in[5];
    const float* wv_b = (const float*)d_in[6];
    const float* wo_w = (const float*)d_in[7];
    const float* fc   = (const float*)d_in[10];
    const float* fs   = (const float*)d_in[11];
    float* out = (float*)d_out;

    const int flash_smem = 30208 * 4;  // 120,832 bytes
    cudaFuncSetAttribute(flash_kernel, cudaFuncAttributeMaxDynamicSharedMemorySize, flash_smem);

    // QKV projections on tf32 tensor cores
    gemm_tf32<<<dim3(QN / 128, MROWS / 128), 256>>>(x, BUF_EXT, wq_w, wq_b, nullptr, BUF_Q, MROWS, QN, DD);
    gemm_tf32<<<dim3(KN / 128, MROWS / 128), 256>>>(x, BUF_EXT, wk_w, wk_b, nullptr, BUF_K, MROWS, KN, DD);
    gemm_tf32<<<dim3(KN / 128, MROWS / 128), 256>>>(x, BUF_EXT, wv_w, wv_b, nullptr, BUF_V, MROWS, KN, DD);

    // RoPE on g_q and g_k
    rope_kernel<<<(MROWS * HH * 64 + MROWS * KVH * 64) / 256, 256>>>(fc, fs);

    // Causal GQA flash attention: g_q,g_k,g_v -> g_o
    flash_kernel<<<dim3(SS / 64, HH, BB), 256, flash_smem>>>();

    // Output projection: g_o @ wo_w^T -> out
    gemm_tf32<<<dim3(QN / 128, MROWS / 128), 256>>>(nullptr, BUF_O, wo_w, nullptr, out, BUF_EXT, MROWS, QN, DD);
}